// round 4
// baseline (speedup 1.0000x reference)
#include <cuda_runtime.h>
#include <cstdint>
#include <cstddef>

#define TOKS 8192
#define DIM  1024
#define HID  4096
#define NEXP 8
#define MT   128
#define NT   128
#define KC   32
#define NSTAGE 4
#define TSTRIDE 144                 // bytes per smem row (36 floats, 16B aligned, conflict-free)
#define A_ST (128 * TSTRIDE)        // 18432 B
#define B_ST (128 * TSTRIDE)
#define STAGE_BYTES (A_ST + B_ST)
#define SMEM_DYN (NSTAGE * STAGE_BYTES)

// ---------------- device scratch (static: allocation-free rule) ----------------
__device__ float g_xr[(size_t)TOKS * DIM];
__device__ float g_W1t[(size_t)NEXP * HID * DIM];   // [e][h][d] K-major, tf32-rounded
__device__ float g_W2t[(size_t)NEXP * DIM * HID];   // [e][d][h] K-major, tf32-rounded
__device__ float g_h[(size_t)TOKS * 2 * HID];
__device__ float g_y[(size_t)TOKS * 2 * DIM];
__device__ int   g_cnt[NEXP];
__device__ int   g_base[NEXP];
__device__ int   g_tok[NEXP * TOKS];
__device__ int   g_ase[TOKS * 2];
__device__ int   g_asp[TOKS * 2];
__device__ float g_asw[TOKS * 2];

// ---------------- helpers ----------------
__device__ __forceinline__ uint32_t smem_u32(const void* p) {
    uint32_t a;
    asm("{ .reg .u64 t; cvta.to.shared.u64 t, %1; cvt.u32.u64 %0, t; }" : "=r"(a) : "l"(p));
    return a;
}
__device__ __forceinline__ float f2tf32(float x) {
    uint32_t u;
    asm("cvt.rna.tf32.f32 %0, %1;" : "=r"(u) : "f"(x));
    return __uint_as_float(u);
}
__device__ __forceinline__ void cp16(uint32_t dst, const float* src, bool full) {
    int sz = full ? 16 : 0;
    asm volatile("cp.async.cg.shared.global [%0], [%1], 16, %2;" :: "r"(dst), "l"(src), "r"(sz));
}
#define CP_COMMIT() asm volatile("cp.async.commit_group;" ::: "memory")

__device__ __forceinline__ void ldsm_x4(uint32_t* r, uint32_t addr) {
    asm volatile("ldmatrix.sync.aligned.m8n8.x4.shared.b16 {%0,%1,%2,%3}, [%4];"
                 : "=r"(r[0]), "=r"(r[1]), "=r"(r[2]), "=r"(r[3]) : "r"(addr));
}
__device__ __forceinline__ void ldsm_x2(uint32_t* r, uint32_t addr) {
    asm volatile("ldmatrix.sync.aligned.m8n8.x2.shared.b16 {%0,%1}, [%2];"
                 : "=r"(r[0]), "=r"(r[1]) : "r"(addr));
}
__device__ __forceinline__ void mma_tf32(float* c, const uint32_t* a, const uint32_t* b) {
    asm volatile(
        "mma.sync.aligned.m16n8k8.row.col.f32.tf32.tf32.f32 "
        "{%0,%1,%2,%3}, {%4,%5,%6,%7}, {%8,%9}, {%0,%1,%2,%3};"
        : "+f"(c[0]), "+f"(c[1]), "+f"(c[2]), "+f"(c[3])
        : "r"(a[0]), "r"(a[1]), "r"(a[2]), "r"(a[3]), "r"(b[0]), "r"(b[1]));
}

// ---------------- kernel 0: zero counters ----------------
__global__ void zero_kernel() {
    if (threadIdx.x < NEXP) g_cnt[threadIdx.x] = 0;
}

// ---------------- kernel 1: gating + routing + tf32-round x ----------------
__global__ void __launch_bounds__(256) gating_kernel(const float* __restrict__ x,
                                                     const float* __restrict__ Wg,
                                                     const float* __restrict__ bg) {
    __shared__ float sWg[NEXP * DIM];   // [j][d]
    const int tid = threadIdx.x;
    for (int i = tid; i < NEXP * DIM; i += 256) {
        int d = i >> 3, j = i & 7;
        sWg[j * DIM + d] = Wg[i];       // Wg is [d][j]
    }
    __syncthreads();
    const int w = tid >> 5, lane = tid & 31;
    const int t = blockIdx.x * 8 + w;
    float acc[NEXP];
#pragma unroll
    for (int j = 0; j < NEXP; j++) acc[j] = 0.f;
    const float* xr = x + (size_t)t * DIM;
    for (int it = 0; it < DIM / 32; ++it) {
        int d = it * 32 + lane;
        float xv = xr[d];
        g_xr[(size_t)t * DIM + d] = f2tf32(xv);
#pragma unroll
        for (int j = 0; j < NEXP; j++) acc[j] = fmaf(xv, sWg[j * DIM + d], acc[j]);
    }
#pragma unroll
    for (int j = 0; j < NEXP; j++)
#pragma unroll
        for (int o = 16; o > 0; o >>= 1) acc[j] += __shfl_xor_sync(0xffffffffu, acc[j], o);
    if (lane == 0) {
        float l[NEXP], mx = -1e30f;
#pragma unroll
        for (int j = 0; j < NEXP; j++) { l[j] = acc[j] + bg[j]; mx = fmaxf(mx, l[j]); }
        float s = 0.f;
#pragma unroll
        for (int j = 0; j < NEXP; j++) { l[j] = expf(l[j] - mx); s += l[j]; }
        float inv = 1.f / s;
#pragma unroll
        for (int j = 0; j < NEXP; j++) l[j] *= inv;
        int i0 = 0;
#pragma unroll
        for (int j = 1; j < NEXP; j++) if (l[j] > l[i0]) i0 = j;
        int i1 = (i0 == 0) ? 1 : 0;
#pragma unroll
        for (int j = 0; j < NEXP; j++) if (j != i0 && j != i1 && l[j] > l[i1]) i1 = j;
#pragma unroll
        for (int j = 0; j < NEXP; j++) if (j != i0 && j < i1 && l[j] >= l[i1]) i1 = j;
        int p0 = atomicAdd(&g_cnt[i0], 1);
        int p1 = atomicAdd(&g_cnt[i1], 1);
        g_tok[i0 * TOKS + p0] = t;
        g_tok[i1 * TOKS + p1] = t;
        g_ase[t * 2 + 0] = i0; g_asp[t * 2 + 0] = p0; g_asw[t * 2 + 0] = l[i0];
        g_ase[t * 2 + 1] = i1; g_asp[t * 2 + 1] = p1; g_asw[t * 2 + 1] = l[i1];
    }
}

// ---------------- kernel 2: exclusive scan ----------------
__global__ void scan_kernel() {
    if (threadIdx.x == 0) {
        int s = 0;
        for (int e = 0; e < NEXP; e++) { g_base[e] = s; s += g_cnt[e]; }
    }
}

// ---------------- kernel 3: transpose + tf32-round weights ----------------
// src [E][R][C] -> dst [E][C][R]
__global__ void transpose_kernel(const float* __restrict__ src, int which, int R, int C) {
    __shared__ float tile[32][33];
    float* dst = which ? g_W2t : g_W1t;
    const int e = blockIdx.z, r0 = blockIdx.y * 32, c0 = blockIdx.x * 32;
    const float* s = src + (size_t)e * R * C;
    float* d = dst + (size_t)e * C * R;
    for (int i = threadIdx.y; i < 32; i += 8)
        tile[i][threadIdx.x] = s[(size_t)(r0 + i) * C + c0 + threadIdx.x];
    __syncthreads();
    for (int i = threadIdx.y; i < 32; i += 8)
        d[(size_t)(c0 + i) * R + r0 + threadIdx.x] = f2tf32(tile[threadIdx.x][i]);
}

// ---------------- kernel 4: tf32 mma.sync GEMM (both phases) ----------------
// grid: (rtile, e, ntile)
template <int PHASE>
__global__ void __launch_bounds__(256) gemm_kernel(const float* __restrict__ bias) {
    constexpr int Kdim = (PHASE == 1) ? DIM : HID;
    constexpr int Ntot = (PHASE == 1) ? HID : DIM;
    constexpr int NK = Kdim / KC;

    const int rtile = blockIdx.x, e = blockIdx.y, ntile = blockIdx.z;
    const int cnt = g_cnt[e];
    const int r_lo = rtile * MT;
    if (r_lo >= cnt) return;
    const int base = g_base[e];
    const int tid = threadIdx.x, wid = tid >> 5, lane = tid & 31;

    extern __shared__ char smem[];
    const uint32_t smA = smem_u32(smem);            // stage s at smA + s*STAGE_BYTES
    const uint32_t smB = smA + A_ST;

    const float* Abase = (PHASE == 1) ? g_xr : g_h;
    const float* Brow0 = ((PHASE == 1) ? g_W1t : g_W2t)
                         + ((size_t)e * Ntot + (size_t)ntile * NT) * Kdim;
    const int* tokp = g_tok + e * TOKS;

    auto load_stage = [&](int kt) {
        const uint32_t sb = (uint32_t)(kt % NSTAGE) * STAGE_BYTES;
        const int k0 = kt * KC;
#pragma unroll
        for (int i = 0; i < 4; i++) {            // A: 128 rows x 8 segs of 16B
            int c = tid + i * 256;
            int r = c >> 3, seg = c & 7;
            int rg = r_lo + r;
            bool ok = rg < cnt;
            const float* src;
            if (PHASE == 1)
                src = Abase + (size_t)(ok ? tokp[rg] : 0) * Kdim + k0 + seg * 4;
            else
                src = Abase + (size_t)(base + (ok ? rg : 0)) * Kdim + k0 + seg * 4;
            cp16(smA + sb + (uint32_t)(r * TSTRIDE + seg * 16), src, ok);
        }
#pragma unroll
        for (int i = 0; i < 4; i++) {            // B: 128 rows x 8 segs
            int c = tid + i * 256;
            int n = c >> 3, seg = c & 7;
            cp16(smB + sb + (uint32_t)(n * TSTRIDE + seg * 16),
                 Brow0 + (size_t)n * Kdim + k0 + seg * 4, true);
        }
        CP_COMMIT();
    };

    // warp tile: 64(m) x 32(n); 2 warps in m, 4 warps in n
    const int wm = (wid & 1) * 64;
    const int wn = (wid >> 1) * 32;
    // ldmatrix lane offsets
    const int amat = lane >> 3;                              // 0..3
    const uint32_t aOff = (uint32_t)((wm + (amat & 1) * 8 + (lane & 7)) * TSTRIDE
                                     + (amat >> 1) * 16);
    const int l2 = lane & 15, bmat = l2 >> 3;                // 0..1
    const uint32_t bOff = (uint32_t)((wn + (l2 & 7)) * TSTRIDE + bmat * 16);

    float acc[4][4][4];
#pragma unroll
    for (int mt = 0; mt < 4; mt++)
#pragma unroll
        for (int nt = 0; nt < 4; nt++)
#pragma unroll
            for (int q = 0; q < 4; q++) acc[mt][nt][q] = 0.f;

#pragma unroll
    for (int s = 0; s < NSTAGE - 1; s++) load_stage(s);

    for (int kt = 0; kt < NK; kt++) {
        if (kt < NK - 1) asm volatile("cp.async.wait_group %0;" :: "n"(NSTAGE - 2) : "memory");
        else             asm volatile("cp.async.wait_group 0;" ::: "memory");
        __syncthreads();
        if (kt + NSTAGE - 1 < NK) load_stage(kt + NSTAGE - 1);

        const uint32_t sb = (uint32_t)(kt % NSTAGE) * STAGE_BYTES;
        const uint32_t aBase = smA + sb + aOff;
        const uint32_t bBase = smB + sb + bOff;
#pragma unroll
        for (int ks = 0; ks < 4; ks++) {
            uint32_t af[4][4], bf[4][2];
#pragma unroll
            for (int mt = 0; mt < 4; mt++)
                ldsm_x4(af[mt], aBase + (uint32_t)(mt * 16 * TSTRIDE + ks * 32));
#pragma unroll
            for (int nt = 0; nt < 4; nt++)
                ldsm_x2(bf[nt], bBase + (uint32_t)(nt * 8 * TSTRIDE + ks * 32));
#pragma unroll
            for (int mt = 0; mt < 4; mt++)
#pragma unroll
                for (int nt = 0; nt < 4; nt++)
                    mma_tf32(acc[mt][nt], af[mt], bf[nt]);
        }
    }

    // epilogue
    const int row_in = lane >> 2;
    const int col_in = (lane & 3) * 2;
    float* Cbase = (PHASE == 1) ? g_h : g_y;
    const float* brow = bias + (size_t)e * Ntot;
#pragma unroll
    for (int mt = 0; mt < 4; mt++) {
#pragma unroll
        for (int half = 0; half < 2; half++) {
            int r = r_lo + wm + mt * 16 + row_in + half * 8;
            if (r < cnt) {
                float* crow = Cbase + (size_t)(base + r) * Ntot;
#pragma unroll
                for (int nt = 0; nt < 4; nt++) {
                    int col = ntile * NT + wn + nt * 8 + col_in;
                    float v0 = acc[mt][nt][half * 2 + 0] + brow[col];
                    float v1 = acc[mt][nt][half * 2 + 1] + brow[col + 1];
                    if (PHASE == 1) {
                        v0 = f2tf32(fmaxf(v0, 0.f));
                        v1 = f2tf32(fmaxf(v1, 0.f));
                    }
                    float2 v = {v0, v1};
                    *(float2*)(crow + col) = v;
                }
            }
        }
    }
}

// ---------------- kernel 5: weighted combine ----------------
__global__ void __launch_bounds__(256) combine_kernel(float* __restrict__ out) {
    const int t = blockIdx.x;
    const int s0 = g_base[g_ase[t * 2 + 0]] + g_asp[t * 2 + 0];
    const int s1 = g_base[g_ase[t * 2 + 1]] + g_asp[t * 2 + 1];
    const float w0 = g_asw[t * 2 + 0], w1 = g_asw[t * 2 + 1];
    const float4* y0 = (const float4*)(g_y + (size_t)s0 * DIM);
    const float4* y1 = (const float4*)(g_y + (size_t)s1 * DIM);
    float4* o = (float4*)(out + (size_t)t * DIM);
    const int i = threadIdx.x;   // 256 threads * 4 floats = 1024 = DIM
    float4 a = y0[i], b = y1[i], r;
    r.x = w0 * a.x + w1 * b.x;
    r.y = w0 * a.y + w1 * b.y;
    r.z = w0 * a.z + w1 * b.z;
    r.w = w0 * a.w + w1 * b.w;
    o[i] = r;
}

// ---------------- launch ----------------
extern "C" void kernel_launch(void* const* d_in, const int* in_sizes, int n_in,
                              void* d_out, int out_size) {
    const float* x  = (const float*)d_in[0];
    const float* Wg = (const float*)d_in[1];
    const float* bg = (const float*)d_in[2];
    const float* W1 = (const float*)d_in[3];
    const float* b1 = (const float*)d_in[4];
    const float* W2 = (const float*)d_in[5];
    const float* b2 = (const float*)d_in[6];
    float* out = (float*)d_out;

    cudaFuncSetAttribute(gemm_kernel<1>, cudaFuncAttributeMaxDynamicSharedMemorySize, SMEM_DYN);
    cudaFuncSetAttribute(gemm_kernel<2>, cudaFuncAttributeMaxDynamicSharedMemorySize, SMEM_DYN);

    zero_kernel<<<1, 32>>>();
    gating_kernel<<<TOKS / 8, 256>>>(x, Wg, bg);
    scan_kernel<<<1, 32>>>();
    transpose_kernel<<<dim3(HID / 32, DIM / 32, NEXP), dim3(32, 8)>>>(W1, 0, DIM, HID);
    transpose_kernel<<<dim3(DIM / 32, HID / 32, NEXP), dim3(32, 8)>>>(W2, 1, HID, DIM);
    gemm_kernel<1><<<dim3(TOKS / MT, NEXP, HID / NT), 256, SMEM_DYN>>>(b1);
    gemm_kernel<2><<<dim3(TOKS / MT, NEXP, DIM / NT), 256, SMEM_DYN>>>(b2);
    combine_kernel<<<TOKS, 256>>>(out);
}

// round 6
// speedup vs baseline: 1.6770x; 1.6770x over previous
#include <cuda_runtime.h>
#include <cuda_fp16.h>
#include <cstdint>
#include <cstddef>

#define TOKS 8192
#define DIM  1024
#define HID  4096
#define NEXP 8
#define MT   128
#define NT   128
#define KC   32                      // k elements (halves) per stage
#define NSTAGE 4
#define TSTRIDE 80                   // bytes per smem row (32 halves + 16B pad)
#define A_ST (128 * TSTRIDE)         // 10240 B
#define B_ST (128 * TSTRIDE)
#define STAGE_BYTES (A_ST + B_ST)    // 20480
#define SMEM_DYN (NSTAGE * STAGE_BYTES)   // 81920

// ---------------- device scratch (static: allocation-free rule) ----------------
__device__ __half g_xr[(size_t)TOKS * DIM];
__device__ __half g_W1t[(size_t)NEXP * HID * DIM];   // [e][h][d] K-major, fp16
__device__ __half g_W2t[(size_t)NEXP * DIM * HID];   // [e][d][h] K-major, fp16
__device__ __half g_h[(size_t)TOKS * 2 * HID];
__device__ float  g_y[(size_t)TOKS * 2 * DIM];
__device__ int    g_cnt[NEXP];
__device__ int    g_base[NEXP];
__device__ int    g_tok[NEXP * TOKS];
__device__ int    g_ase[TOKS * 2];
__device__ int    g_asp[TOKS * 2];
__device__ float  g_asw[TOKS * 2];

// ---------------- helpers ----------------
__device__ __forceinline__ uint32_t smem_u32(const void* p) {
    uint32_t a;
    asm("{ .reg .u64 t; cvta.to.shared.u64 t, %1; cvt.u32.u64 %0, t; }" : "=r"(a) : "l"(p));
    return a;
}
__device__ __forceinline__ void cp16(uint32_t dst, const void* src, bool full) {
    int sz = full ? 16 : 0;
    asm volatile("cp.async.cg.shared.global [%0], [%1], 16, %2;" :: "r"(dst), "l"(src), "r"(sz));
}
#define CP_COMMIT() asm volatile("cp.async.commit_group;" ::: "memory")

__device__ __forceinline__ void ldsm_x4(uint32_t* r, uint32_t addr) {
    asm volatile("ldmatrix.sync.aligned.m8n8.x4.shared.b16 {%0,%1,%2,%3}, [%4];"
                 : "=r"(r[0]), "=r"(r[1]), "=r"(r[2]), "=r"(r[3]) : "r"(addr));
}
__device__ __forceinline__ void ldsm_x2(uint32_t* r, uint32_t addr) {
    asm volatile("ldmatrix.sync.aligned.m8n8.x2.shared.b16 {%0,%1}, [%2];"
                 : "=r"(r[0]), "=r"(r[1]) : "r"(addr));
}
__device__ __forceinline__ void mma_f16(float* c, const uint32_t* a, const uint32_t* b) {
    asm volatile(
        "mma.sync.aligned.m16n8k16.row.col.f32.f16.f16.f32 "
        "{%0,%1,%2,%3}, {%4,%5,%6,%7}, {%8,%9}, {%0,%1,%2,%3};"
        : "+f"(c[0]), "+f"(c[1]), "+f"(c[2]), "+f"(c[3])
        : "r"(a[0]), "r"(a[1]), "r"(a[2]), "r"(a[3]), "r"(b[0]), "r"(b[1]));
}

// ---------------- kernel 0: zero counters ----------------
__global__ void zero_kernel() {
    if (threadIdx.x < NEXP) g_cnt[threadIdx.x] = 0;
}

// ---------------- kernel 1: gating + routing + fp16-round x ----------------
__global__ void __launch_bounds__(256) gating_kernel(const float* __restrict__ x,
                                                     const float* __restrict__ Wg,
                                                     const float* __restrict__ bg) {
    __shared__ float sWg[NEXP * DIM];   // [j][d]
    const int tid = threadIdx.x;
    for (int i = tid; i < NEXP * DIM; i += 256) {
        int d = i >> 3, j = i & 7;
        sWg[j * DIM + d] = Wg[i];       // Wg is [d][j]
    }
    __syncthreads();
    const int w = tid >> 5, lane = tid & 31;
    const int t = blockIdx.x * 8 + w;
    float acc[NEXP];
#pragma unroll
    for (int j = 0; j < NEXP; j++) acc[j] = 0.f;
    const float* xr = x + (size_t)t * DIM;
    for (int it = 0; it < DIM / 32; ++it) {
        int d = it * 32 + lane;
        float xv = xr[d];
        g_xr[(size_t)t * DIM + d] = __float2half_rn(xv);
#pragma unroll
        for (int j = 0; j < NEXP; j++) acc[j] = fmaf(xv, sWg[j * DIM + d], acc[j]);
    }
#pragma unroll
    for (int j = 0; j < NEXP; j++)
#pragma unroll
        for (int o = 16; o > 0; o >>= 1) acc[j] += __shfl_xor_sync(0xffffffffu, acc[j], o);
    if (lane == 0) {
        float l[NEXP], mx = -1e30f;
#pragma unroll
        for (int j = 0; j < NEXP; j++) { l[j] = acc[j] + bg[j]; mx = fmaxf(mx, l[j]); }
        float s = 0.f;
#pragma unroll
        for (int j = 0; j < NEXP; j++) { l[j] = expf(l[j] - mx); s += l[j]; }
        float inv = 1.f / s;
#pragma unroll
        for (int j = 0; j < NEXP; j++) l[j] *= inv;
        int i0 = 0;
#pragma unroll
        for (int j = 1; j < NEXP; j++) if (l[j] > l[i0]) i0 = j;
        int i1 = (i0 == 0) ? 1 : 0;
#pragma unroll
        for (int j = 0; j < NEXP; j++) if (j != i0 && j != i1 && l[j] > l[i1]) i1 = j;
#pragma unroll
        for (int j = 0; j < NEXP; j++) if (j != i0 && j < i1 && l[j] >= l[i1]) i1 = j;
        int p0 = atomicAdd(&g_cnt[i0], 1);
        int p1 = atomicAdd(&g_cnt[i1], 1);
        g_tok[i0 * TOKS + p0] = t;
        g_tok[i1 * TOKS + p1] = t;
        g_ase[t * 2 + 0] = i0; g_asp[t * 2 + 0] = p0; g_asw[t * 2 + 0] = l[i0];
        g_ase[t * 2 + 1] = i1; g_asp[t * 2 + 1] = p1; g_asw[t * 2 + 1] = l[i1];
    }
}

// ---------------- kernel 2: exclusive scan ----------------
__global__ void scan_kernel() {
    if (threadIdx.x == 0) {
        int s = 0;
        for (int e = 0; e < NEXP; e++) { g_base[e] = s; s += g_cnt[e]; }
    }
}

// ---------------- kernel 3: transpose + fp16-round weights ----------------
// src [E][R][C] -> dst [E][C][R]
__global__ void transpose_kernel(const float* __restrict__ src, int which, int R, int C) {
    __shared__ float tile[32][33];
    __half* dst = which ? g_W2t : g_W1t;
    const int e = blockIdx.z, r0 = blockIdx.y * 32, c0 = blockIdx.x * 32;
    const float* s = src + (size_t)e * R * C;
    __half* d = dst + (size_t)e * C * R;
    for (int i = threadIdx.y; i < 32; i += 8)
        tile[i][threadIdx.x] = s[(size_t)(r0 + i) * C + c0 + threadIdx.x];
    __syncthreads();
    for (int i = threadIdx.y; i < 32; i += 8)
        d[(size_t)(c0 + i) * R + r0 + threadIdx.x] = __float2half_rn(tile[threadIdx.x][i]);
}

// ---------------- kernel 4: fp16 mma.sync GEMM (both phases) ----------------
// grid: (rtile, e, ntile)
template <int PHASE>
__global__ void __launch_bounds__(256) gemm_kernel(const float* __restrict__ bias) {
    constexpr int Kdim = (PHASE == 1) ? DIM : HID;
    constexpr int Ntot = (PHASE == 1) ? HID : DIM;
    constexpr int NK = Kdim / KC;

    const int rtile = blockIdx.x, e = blockIdx.y, ntile = blockIdx.z;
    const int cnt = g_cnt[e];
    const int r_lo = rtile * MT;
    if (r_lo >= cnt) return;
    const int base = g_base[e];
    const int tid = threadIdx.x, wid = tid >> 5, lane = tid & 31;

    extern __shared__ char smem[];
    const uint32_t smA = smem_u32(smem);            // stage s at smA + s*STAGE_BYTES
    const uint32_t smB = smA + A_ST;

    const __half* Abase = (PHASE == 1) ? g_xr : g_h;
    const __half* Brow0 = ((PHASE == 1) ? g_W1t : g_W2t)
                          + ((size_t)e * Ntot + (size_t)ntile * NT) * Kdim;
    const int* tokp = g_tok + e * TOKS;

    auto load_stage = [&](int kt) {
        const uint32_t sb = (uint32_t)(kt % NSTAGE) * STAGE_BYTES;
        const int k0 = kt * KC;
#pragma unroll
        for (int i = 0; i < 2; i++) {            // A: 128 rows x 4 segs of 16B (8 halves)
            int c = tid + i * 256;
            int r = c >> 2, seg = c & 3;
            int rg = r_lo + r;
            bool ok = rg < cnt;
            const __half* src;
            if (PHASE == 1)
                src = Abase + (size_t)(ok ? tokp[rg] : 0) * Kdim + k0 + seg * 8;
            else
                src = Abase + (size_t)(base + (ok ? rg : 0)) * Kdim + k0 + seg * 8;
            cp16(smA + sb + (uint32_t)(r * TSTRIDE + seg * 16), src, ok);
        }
#pragma unroll
        for (int i = 0; i < 2; i++) {            // B: 128 rows x 4 segs
            int c = tid + i * 256;
            int n = c >> 2, seg = c & 3;
            cp16(smB + sb + (uint32_t)(n * TSTRIDE + seg * 16),
                 Brow0 + (size_t)n * Kdim + k0 + seg * 8, true);
        }
        CP_COMMIT();
    };

    // warp tile: 64(m) x 32(n); 2 warps in m, 4 warps in n
    const int wm = (wid & 1) * 64;
    const int wn = (wid >> 1) * 32;
    // ldmatrix lane offsets (16B chunk = 8 halves = k8)
    const int amat = lane >> 3;                              // 0..3
    const uint32_t aOff = (uint32_t)((wm + (amat & 1) * 8 + (lane & 7)) * TSTRIDE
                                     + (amat >> 1) * 16);
    const int l2 = lane & 15, bmat = l2 >> 3;                // 0..1
    const uint32_t bOff = (uint32_t)((wn + (l2 & 7)) * TSTRIDE + bmat * 16);

    float acc[4][4][4];
#pragma unroll
    for (int mt = 0; mt < 4; mt++)
#pragma unroll
        for (int nt = 0; nt < 4; nt++)
#pragma unroll
            for (int q = 0; q < 4; q++) acc[mt][nt][q] = 0.f;

#pragma unroll
    for (int s = 0; s < NSTAGE - 1; s++) load_stage(s);

    for (int kt = 0; kt < NK; kt++) {
        if (kt < NK - 1) asm volatile("cp.async.wait_group %0;" :: "n"(NSTAGE - 2) : "memory");
        else             asm volatile("cp.async.wait_group 0;" ::: "memory");
        __syncthreads();
        if (kt + NSTAGE - 1 < NK) load_stage(kt + NSTAGE - 1);

        const uint32_t sb = (uint32_t)(kt % NSTAGE) * STAGE_BYTES;
        const uint32_t aBase = smA + sb + aOff;
        const uint32_t bBase = smB + sb + bOff;
#pragma unroll
        for (int ks = 0; ks < 2; ks++) {         // two k16 steps per 32-k stage
            uint32_t af[4][4], bf[4][2];
#pragma unroll
            for (int mt = 0; mt < 4; mt++)
                ldsm_x4(af[mt], aBase + (uint32_t)(mt * 16 * TSTRIDE + ks * 32));
#pragma unroll
            for (int nt = 0; nt < 4; nt++)
                ldsm_x2(bf[nt], bBase + (uint32_t)(nt * 8 * TSTRIDE + ks * 32));
#pragma unroll
            for (int mt = 0; mt < 4; mt++)
#pragma unroll
                for (int nt = 0; nt < 4; nt++)
                    mma_f16(acc[mt][nt], af[mt], bf[nt]);
        }
    }

    // epilogue
    const int row_in = lane >> 2;
    const int col_in = (lane & 3) * 2;
    const float* brow = bias + (size_t)e * Ntot;
#pragma unroll
    for (int mt = 0; mt < 4; mt++) {
#pragma unroll
        for (int half = 0; half < 2; half++) {
            int r = r_lo + wm + mt * 16 + row_in + half * 8;
            if (r < cnt) {
#pragma unroll
                for (int nt = 0; nt < 4; nt++) {
                    int col = ntile * NT + wn + nt * 8 + col_in;
                    float v0 = acc[mt][nt][half * 2 + 0] + brow[col];
                    float v1 = acc[mt][nt][half * 2 + 1] + brow[col + 1];
                    if (PHASE == 1) {
                        __half2 hv;
                        hv.x = __float2half_rn(fmaxf(v0, 0.f));
                        hv.y = __float2half_rn(fmaxf(v1, 0.f));
                        *(__half2*)(g_h + (size_t)(base + r) * Ntot + col) = hv;
                    } else {
                        float2 v = {v0, v1};
                        *(float2*)(g_y + (size_t)(base + r) * Ntot + col) = v;
                    }
                }
            }
        }
    }
}

// ---------------- kernel 5: weighted combine ----------------
__global__ void __launch_bounds__(256) combine_kernel(float* __restrict__ out) {
    const int t = blockIdx.x;
    const int s0 = g_base[g_ase[t * 2 + 0]] + g_asp[t * 2 + 0];
    const int s1 = g_base[g_ase[t * 2 + 1]] + g_asp[t * 2 + 1];
    const float w0 = g_asw[t * 2 + 0], w1 = g_asw[t * 2 + 1];
    const float4* y0 = (const float4*)(g_y + (size_t)s0 * DIM);
    const float4* y1 = (const float4*)(g_y + (size_t)s1 * DIM);
    float4* o = (float4*)(out + (size_t)t * DIM);
    const int i = threadIdx.x;   // 256 threads * 4 floats = 1024 = DIM
    float4 a = y0[i], b = y1[i], r;
    r.x = w0 * a.x + w1 * b.x;
    r.y = w0 * a.y + w1 * b.y;
    r.z = w0 * a.z + w1 * b.z;
    r.w = w0 * a.w + w1 * b.w;
    o[i] = r;
}

// ---------------- launch ----------------
extern "C" void kernel_launch(void* const* d_in, const int* in_sizes, int n_in,
                              void* d_out, int out_size) {
    const float* x  = (const float*)d_in[0];
    const float* Wg = (const float*)d_in[1];
    const float* bg = (const float*)d_in[2];
    const float* W1 = (const float*)d_in[3];
    const float* b1 = (const float*)d_in[4];
    const float* W2 = (const float*)d_in[5];
    const float* b2 = (const float*)d_in[6];
    float* out = (float*)d_out;

    cudaFuncSetAttribute(gemm_kernel<1>, cudaFuncAttributeMaxDynamicSharedMemorySize, SMEM_DYN);
    cudaFuncSetAttribute(gemm_kernel<2>, cudaFuncAttributeMaxDynamicSharedMemorySize, SMEM_DYN);

    zero_kernel<<<1, 32>>>();
    gating_kernel<<<TOKS / 8, 256>>>(x, Wg, bg);
    scan_kernel<<<1, 32>>>();
    transpose_kernel<<<dim3(HID / 32, DIM / 32, NEXP), dim3(32, 8)>>>(W1, 0, DIM, HID);
    transpose_kernel<<<dim3(DIM / 32, HID / 32, NEXP), dim3(32, 8)>>>(W2, 1, HID, DIM);
    gemm_kernel<1><<<dim3(TOKS / MT, NEXP, HID / NT), 256, SMEM_DYN>>>(b1);
    gemm_kernel<2><<<dim3(TOKS / MT, NEXP, DIM / NT), 256, SMEM_DYN>>>(b2);
    combine_kernel<<<TOKS, 256>>>(out);
}

// round 12
// speedup vs baseline: 2.0257x; 1.2079x over previous
#include <cuda_runtime.h>
#include <cuda_fp16.h>
#include <cstdint>
#include <cstddef>

#define TOKS 8192
#define DIM  1024
#define HID  4096
#define NEXP 8
#define MT   128
#define NT   128
#define KC   32                      // k elements (halves) per stage
#define NSTAGE 4
#define TSTRIDE 80                   // bytes per smem row (32 halves + 16B pad)
#define A_ST (128 * TSTRIDE)         // 10240 B
#define B_ST (128 * TSTRIDE)
#define STAGE_BYTES (A_ST + B_ST)    // 20480
#define SMEM_DYN (NSTAGE * STAGE_BYTES)   // 81920

// ---------------- device scratch (static: allocation-free rule) ----------------
__device__ __half g_xr[(size_t)TOKS * DIM];
__device__ __half g_W1t[(size_t)NEXP * HID * DIM];   // [e][h][d] K-major, fp16
__device__ __half g_W2t[(size_t)NEXP * DIM * HID];   // [e][d][h] K-major, fp16
__device__ __half g_h[(size_t)TOKS * 2 * HID];
__device__ float  g_y[(size_t)TOKS * 2 * DIM];
__device__ int    g_cnt[NEXP];
__device__ int    g_base[NEXP];
__device__ int    g_tok[NEXP * TOKS];
__device__ int    g_ase[TOKS * 2];
__device__ int    g_asp[TOKS * 2];
__device__ float  g_asw[TOKS * 2];

// ---------------- helpers ----------------
__device__ __forceinline__ uint32_t smem_u32(const void* p) {
    uint32_t a;
    asm("{ .reg .u64 t; cvta.to.shared.u64 t, %1; cvt.u32.u64 %0, t; }" : "=r"(a) : "l"(p));
    return a;
}
__device__ __forceinline__ void cp16(uint32_t dst, const void* src, bool full) {
    int sz = full ? 16 : 0;
    asm volatile("cp.async.cg.shared.global [%0], [%1], 16, %2;" :: "r"(dst), "l"(src), "r"(sz));
}
#define CP_COMMIT() asm volatile("cp.async.commit_group;" ::: "memory")

__device__ __forceinline__ void ldsm_x4(uint32_t* r, uint32_t addr) {
    asm volatile("ldmatrix.sync.aligned.m8n8.x4.shared.b16 {%0,%1,%2,%3}, [%4];"
                 : "=r"(r[0]), "=r"(r[1]), "=r"(r[2]), "=r"(r[3]) : "r"(addr));
}
__device__ __forceinline__ void ldsm_x2(uint32_t* r, uint32_t addr) {
    asm volatile("ldmatrix.sync.aligned.m8n8.x2.shared.b16 {%0,%1}, [%2];"
                 : "=r"(r[0]), "=r"(r[1]) : "r"(addr));
}
__device__ __forceinline__ void mma_f16(float* c, const uint32_t* a, const uint32_t* b) {
    asm volatile(
        "mma.sync.aligned.m16n8k16.row.col.f32.f16.f16.f32 "
        "{%0,%1,%2,%3}, {%4,%5,%6,%7}, {%8,%9}, {%0,%1,%2,%3};"
        : "+f"(c[0]), "+f"(c[1]), "+f"(c[2]), "+f"(c[3])
        : "r"(a[0]), "r"(a[1]), "r"(a[2]), "r"(a[3]), "r"(b[0]), "r"(b[1]));
}

// ---------------- kernel 0: zero counters ----------------
__global__ void zero_kernel() {
    if (threadIdx.x < NEXP) g_cnt[threadIdx.x] = 0;
}

// ---------------- kernel 1: gating + routing + fp16-round x ----------------
__global__ void __launch_bounds__(256) gating_kernel(const float* __restrict__ x,
                                                     const float* __restrict__ Wg,
                                                     const float* __restrict__ bg) {
    __shared__ float sWg[NEXP * DIM];   // [j][d]
    const int tid = threadIdx.x;
    for (int i = tid; i < NEXP * DIM; i += 256) {
        int d = i >> 3, j = i & 7;
        sWg[j * DIM + d] = Wg[i];       // Wg is [d][j]
    }
    __syncthreads();
    const int w = tid >> 5, lane = tid & 31;
    const int t = blockIdx.x * 8 + w;
    float acc[NEXP];
#pragma unroll
    for (int j = 0; j < NEXP; j++) acc[j] = 0.f;
    const float* xr = x + (size_t)t * DIM;
    for (int it = 0; it < DIM / 32; ++it) {
        int d = it * 32 + lane;
        float xv = xr[d];
        g_xr[(size_t)t * DIM + d] = __float2half_rn(xv);
#pragma unroll
        for (int j = 0; j < NEXP; j++) acc[j] = fmaf(xv, sWg[j * DIM + d], acc[j]);
    }
#pragma unroll
    for (int j = 0; j < NEXP; j++)
#pragma unroll
        for (int o = 16; o > 0; o >>= 1) acc[j] += __shfl_xor_sync(0xffffffffu, acc[j], o);
    if (lane == 0) {
        float l[NEXP], mx = -1e30f;
#pragma unroll
        for (int j = 0; j < NEXP; j++) { l[j] = acc[j] + bg[j]; mx = fmaxf(mx, l[j]); }
        float s = 0.f;
#pragma unroll
        for (int j = 0; j < NEXP; j++) { l[j] = expf(l[j] - mx); s += l[j]; }
        float inv = 1.f / s;
#pragma unroll
        for (int j = 0; j < NEXP; j++) l[j] *= inv;
        int i0 = 0;
#pragma unroll
        for (int j = 1; j < NEXP; j++) if (l[j] > l[i0]) i0 = j;
        int i1 = (i0 == 0) ? 1 : 0;
#pragma unroll
        for (int j = 0; j < NEXP; j++) if (j != i0 && j != i1 && l[j] > l[i1]) i1 = j;
#pragma unroll
        for (int j = 0; j < NEXP; j++) if (j != i0 && j < i1 && l[j] >= l[i1]) i1 = j;
        int p0 = atomicAdd(&g_cnt[i0], 1);
        int p1 = atomicAdd(&g_cnt[i1], 1);
        g_tok[i0 * TOKS + p0] = t;
        g_tok[i1 * TOKS + p1] = t;
        g_ase[t * 2 + 0] = i0; g_asp[t * 2 + 0] = p0; g_asw[t * 2 + 0] = l[i0];
        g_ase[t * 2 + 1] = i1; g_asp[t * 2 + 1] = p1; g_asw[t * 2 + 1] = l[i1];
    }
}

// ---------------- kernel 2: exclusive scan ----------------
__global__ void scan_kernel() {
    if (threadIdx.x == 0) {
        int s = 0;
        for (int e = 0; e < NEXP; e++) { g_base[e] = s; s += g_cnt[e]; }
    }
}

// ---------------- kernel 3: transpose + fp16 convert, 64x32 tiles ----------------
// src [E][R][C] fp32 -> dst [E][C][R] fp16.  Reads 128B rows, writes 128B rows.
__global__ void __launch_bounds__(256) transpose_kernel(const float* __restrict__ src,
                                                        int which, int R, int C) {
    __shared__ float tile[64][33];
    __half* dst = which ? g_W2t : g_W1t;
    const int e = blockIdx.z, r0 = blockIdx.y * 64, c0 = blockIdx.x * 32;
    const float* s = src + (size_t)e * R * C;
    __half* d = dst + (size_t)e * C * R;
    const int tid = threadIdx.x;
    const int hc = tid & 31, dr0 = tid >> 5;
#pragma unroll
    for (int i = 0; i < 8; i++)
        tile[dr0 + i * 8][hc] = s[(size_t)(r0 + dr0 + i * 8) * C + c0 + hc];
    __syncthreads();
    const int h = tid >> 3, ch = tid & 7;     // output row (c), 8-half chunk (r)
    __half hv[8];
#pragma unroll
    for (int j = 0; j < 8; j++) hv[j] = __float2half_rn(tile[ch * 8 + j][h]);
    *(uint4*)(d + (size_t)(c0 + h) * R + r0 + ch * 8) = *(uint4*)hv;
}

// ---------------- kernel 4: fp16 mma.sync GEMM (both phases) ----------------
// grid: (rtile, e, ntile)
template <int PHASE>
__global__ void __launch_bounds__(256, 2) gemm_kernel(const float* __restrict__ bias) {
    constexpr int Kdim = (PHASE == 1) ? DIM : HID;
    constexpr int Ntot = (PHASE == 1) ? HID : DIM;
    constexpr int NK = Kdim / KC;

    const int rtile = blockIdx.x, e = blockIdx.y, ntile = blockIdx.z;
    const int cnt = g_cnt[e];
    const int r_lo = rtile * MT;
    if (r_lo >= cnt) return;
    const int base = g_base[e];
    const int tid = threadIdx.x, wid = tid >> 5, lane = tid & 31;

    extern __shared__ char smem[];
    const uint32_t smA = smem_u32(smem);            // stage s at smA + s*STAGE_BYTES
    const uint32_t smB = smA + A_ST;

    const __half* Abase = (PHASE == 1) ? g_xr : g_h;
    const __half* Brow0 = ((PHASE == 1) ? g_W1t : g_W2t)
                          + ((size_t)e * Ntot + (size_t)ntile * NT) * Kdim;   // [n][k]
    const int* tokp = g_tok + e * TOKS;

    auto load_stage = [&](int kt) {
        const uint32_t sb = (uint32_t)(kt % NSTAGE) * STAGE_BYTES;
        const int k0 = kt * KC;
#pragma unroll
        for (int i = 0; i < 2; i++) {            // A: 128 rows x 4 segs of 16B (8 halves)
            int c = tid + i * 256;
            int r = c >> 2, seg = c & 3;
            int rg = r_lo + r;
            bool ok = rg < cnt;
            const __half* src;
            if (PHASE == 1)
                src = Abase + (size_t)(ok ? tokp[rg] : 0) * Kdim + k0 + seg * 8;
            else
                src = Abase + (size_t)(base + (ok ? rg : 0)) * Kdim + k0 + seg * 8;
            cp16(smA + sb + (uint32_t)(r * TSTRIDE + seg * 16), src, ok);
        }
#pragma unroll
        for (int i = 0; i < 2; i++) {            // B: 128 n-rows x 4 segs
            int c = tid + i * 256;
            int n = c >> 2, seg = c & 3;
            cp16(smB + sb + (uint32_t)(n * TSTRIDE + seg * 16),
                 Brow0 + (size_t)n * Kdim + k0 + seg * 8, true);
        }
        CP_COMMIT();
    };

    // warp tile: 64(m) x 32(n); 2 warps in m, 4 warps in n
    const int wm = (wid & 1) * 64;
    const int wn = (wid >> 1) * 32;
    // ldmatrix lane offsets (16B chunk = 8 halves = k8)
    const int amat = lane >> 3;                              // 0..3
    const uint32_t aOff = (uint32_t)((wm + (amat & 1) * 8 + (lane & 7)) * TSTRIDE
                                     + (amat >> 1) * 16);
    const int l2 = lane & 15, bmat = l2 >> 3;                // 0..1
    const uint32_t bOff = (uint32_t)((wn + (l2 & 7)) * TSTRIDE + bmat * 16);

    float acc[4][4][4];
#pragma unroll
    for (int mt = 0; mt < 4; mt++)
#pragma unroll
        for (int nt = 0; nt < 4; nt++)
#pragma unroll
            for (int q = 0; q < 4; q++) acc[mt][nt][q] = 0.f;

#pragma unroll
    for (int s = 0; s < NSTAGE - 1; s++) load_stage(s);

    for (int kt = 0; kt < NK; kt++) {
        if (kt < NK - 1) asm volatile("cp.async.wait_group %0;" :: "n"(NSTAGE - 2) : "memory");
        else             asm volatile("cp.async.wait_group 0;" ::: "memory");
        __syncthreads();
        if (kt + NSTAGE - 1 < NK) load_stage(kt + NSTAGE - 1);

        const uint32_t sb = (uint32_t)(kt % NSTAGE) * STAGE_BYTES;
        const uint32_t aBase = smA + sb + aOff;
        const uint32_t bBase = smB + sb + bOff;
#pragma unroll
        for (int ks = 0; ks < 2; ks++) {         // two k16 steps per 32-k stage
            uint32_t af[4][4], bf[4][2];
#pragma unroll
            for (int mt = 0; mt < 4; mt++)
                ldsm_x4(af[mt], aBase + (uint32_t)(mt * 16 * TSTRIDE + ks * 32));
#pragma unroll
            for (int nt = 0; nt < 4; nt++)
                ldsm_x2(bf[nt], bBase + (uint32_t)(nt * 8 * TSTRIDE + ks * 32));
#pragma unroll
            for (int mt = 0; mt < 4; mt++)
#pragma unroll
                for (int nt = 0; nt < 4; nt++)
                    mma_f16(acc[mt][nt], af[mt], bf[nt]);
        }
    }

    // epilogue
    const int row_in = lane >> 2;
    const int col_in = (lane & 3) * 2;
    const float* brow = bias + (size_t)e * Ntot;
#pragma unroll
    for (int mt = 0; mt < 4; mt++) {
#pragma unroll
        for (int half = 0; half < 2; half++) {
            int r = r_lo + wm + mt * 16 + row_in + half * 8;
            if (r < cnt) {
#pragma unroll
                for (int nt = 0; nt < 4; nt++) {
                    int col = ntile * NT + wn + nt * 8 + col_in;
                    float v0 = acc[mt][nt][half * 2 + 0] + brow[col];
                    float v1 = acc[mt][nt][half * 2 + 1] + brow[col + 1];
                    if (PHASE == 1) {
                        __half2 hv;
                        hv.x = __float2half_rn(fmaxf(v0, 0.f));
                        hv.y = __float2half_rn(fmaxf(v1, 0.f));
                        *(__half2*)(g_h + (size_t)(base + r) * Ntot + col) = hv;
                    } else {
                        float2 v = {v0, v1};
                        *(float2*)(g_y + (size_t)(base + r) * Ntot + col) = v;
                    }
                }
            }
        }
    }
}

// ---------------- kernel 5: weighted combine ----------------
__global__ void __launch_bounds__(256) combine_kernel(float* __restrict__ out) {
    const int t = blockIdx.x;
    const int s0 = g_base[g_ase[t * 2 + 0]] + g_asp[t * 2 + 0];
    const int s1 = g_base[g_ase[t * 2 + 1]] + g_asp[t * 2 + 1];
    const float w0 = g_asw[t * 2 + 0], w1 = g_asw[t * 2 + 1];
    const float4* y0 = (const float4*)(g_y + (size_t)s0 * DIM);
    const float4* y1 = (const float4*)(g_y + (size_t)s1 * DIM);
    float4* o = (float4*)(out + (size_t)t * DIM);
    const int i = threadIdx.x;   // 256 threads * 4 floats = 1024 = DIM
    float4 a = y0[i], b = y1[i], r;
    r.x = w0 * a.x + w1 * b.x;
    r.y = w0 * a.y + w1 * b.y;
    r.z = w0 * a.z + w1 * b.z;
    r.w = w0 * a.w + w1 * b.w;
    o[i] = r;
}

// ---------------- launch ----------------
extern "C" void kernel_launch(void* const* d_in, const int* in_sizes, int n_in,
                              void* d_out, int out_size) {
    const float* x  = (const float*)d_in[0];
    const float* Wg = (const float*)d_in[1];
    const float* bg = (const float*)d_in[2];
    const float* W1 = (const float*)d_in[3];
    const float* b1 = (const float*)d_in[4];
    const float* W2 = (const float*)d_in[5];
    const float* b2 = (const float*)d_in[6];
    float* out = (float*)d_out;

    cudaFuncSetAttribute(gemm_kernel<1>, cudaFuncAttributeMaxDynamicSharedMemorySize, SMEM_DYN);
    cudaFuncSetAttribute(gemm_kernel<2>, cudaFuncAttributeMaxDynamicSharedMemorySize, SMEM_DYN);

    zero_kernel<<<1, 32>>>();
    gating_kernel<<<TOKS / 8, 256>>>(x, Wg, bg);
    scan_kernel<<<1, 32>>>();
    // W1 [E][D][H] -> g_W1t [E][H][D]:  R=D, C=H
    transpose_kernel<<<dim3(HID / 32, DIM / 64, NEXP), 256>>>(W1, 0, DIM, HID);
    // W2 [E][H][D] -> g_W2t [E][D][H]:  R=H, C=D
    transpose_kernel<<<dim3(DIM / 32, HID / 64, NEXP), 256>>>(W2, 1, HID, DIM);
    gemm_kernel<1><<<dim3(TOKS / MT, NEXP, HID / NT), 256, SMEM_DYN>>>(b1);
    gemm_kernel<2><<<dim3(TOKS / MT, NEXP, DIM / NT), 256, SMEM_DYN>>>(b2);
    combine_kernel<<<TOKS, 256>>>(out);
}

// round 14
// speedup vs baseline: 2.1770x; 1.0747x over previous
#include <cuda_runtime.h>
#include <cuda_fp16.h>
#include <cstdint>
#include <cstddef>

#define TOKS 8192
#define DIM  1024
#define HID  4096
#define NEXP 8
#define MT   128
#define NT   128
#define KC   32                      // k elements (halves) per stage
#define NSTAGE 4
#define TSTRIDE 80                   // bytes per smem row (32 halves + 16B pad)
#define A_ST (128 * TSTRIDE)         // 10240 B
#define B_ST (128 * TSTRIDE)
#define STAGE_BYTES (A_ST + B_ST)    // 20480
#define SMEM_DYN (NSTAGE * STAGE_BYTES)   // 81920

// ---------------- device scratch (static: allocation-free rule) ----------------
__device__ __half g_xr[(size_t)TOKS * DIM];
__device__ __half g_W1t[(size_t)NEXP * HID * DIM];   // [e][h][d] K-major, fp16
__device__ __half g_W2t[(size_t)NEXP * DIM * HID];   // [e][d][h] K-major, fp16
__device__ __half g_h[(size_t)TOKS * 2 * HID];
__device__ __half g_y[(size_t)TOKS * 2 * DIM];
__device__ int    g_cnt[NEXP];
__device__ int    g_base[NEXP];
__device__ int    g_tok[NEXP * TOKS];
__device__ int    g_ase[TOKS * 2];
__device__ int    g_asp[TOKS * 2];
__device__ float  g_asw[TOKS * 2];

// ---------------- helpers ----------------
__device__ __forceinline__ uint32_t smem_u32(const void* p) {
    uint32_t a;
    asm("{ .reg .u64 t; cvta.to.shared.u64 t, %1; cvt.u32.u64 %0, t; }" : "=r"(a) : "l"(p));
    return a;
}
__device__ __forceinline__ void cp16(uint32_t dst, const void* src, bool full) {
    int sz = full ? 16 : 0;
    asm volatile("cp.async.cg.shared.global [%0], [%1], 16, %2;" :: "r"(dst), "l"(src), "r"(sz));
}
#define CP_COMMIT() asm volatile("cp.async.commit_group;" ::: "memory")

__device__ __forceinline__ void ldsm_x4(uint32_t* r, uint32_t addr) {
    asm volatile("ldmatrix.sync.aligned.m8n8.x4.shared.b16 {%0,%1,%2,%3}, [%4];"
                 : "=r"(r[0]), "=r"(r[1]), "=r"(r[2]), "=r"(r[3]) : "r"(addr));
}
__device__ __forceinline__ void mma_f16(float* c, const uint32_t* a, const uint32_t* b) {
    asm volatile(
        "mma.sync.aligned.m16n8k16.row.col.f32.f16.f16.f32 "
        "{%0,%1,%2,%3}, {%4,%5,%6,%7}, {%8,%9}, {%0,%1,%2,%3};"
        : "+f"(c[0]), "+f"(c[1]), "+f"(c[2]), "+f"(c[3])
        : "r"(a[0]), "r"(a[1]), "r"(a[2]), "r"(a[3]), "r"(b[0]), "r"(b[1]));
}

// ---------------- kernel 0: zero counters ----------------
__global__ void zero_kernel() {
    if (threadIdx.x < NEXP) g_cnt[threadIdx.x] = 0;
}

// ---------------- kernel 1: gating + routing + fp16-round x ----------------
__global__ void __launch_bounds__(256) gating_kernel(const float* __restrict__ x,
                                                     const float* __restrict__ Wg,
                                                     const float* __restrict__ bg) {
    __shared__ float sWg[NEXP * DIM];   // [j][d]
    const int tid = threadIdx.x;
    for (int i = tid; i < NEXP * DIM; i += 256) {
        int d = i >> 3, j = i & 7;
        sWg[j * DIM + d] = Wg[i];       // Wg is [d][j]
    }
    __syncthreads();
    const int w = tid >> 5, lane = tid & 31;
    const int t = blockIdx.x * 8 + w;
    float acc[NEXP];
#pragma unroll
    for (int j = 0; j < NEXP; j++) acc[j] = 0.f;
    const float* xr = x + (size_t)t * DIM;
    for (int it = 0; it < DIM / 32; ++it) {
        int d = it * 32 + lane;
        float xv = xr[d];
        g_xr[(size_t)t * DIM + d] = __float2half_rn(xv);
#pragma unroll
        for (int j = 0; j < NEXP; j++) acc[j] = fmaf(xv, sWg[j * DIM + d], acc[j]);
    }
#pragma unroll
    for (int j = 0; j < NEXP; j++)
#pragma unroll
        for (int o = 16; o > 0; o >>= 1) acc[j] += __shfl_xor_sync(0xffffffffu, acc[j], o);
    if (lane == 0) {
        float l[NEXP], mx = -1e30f;
#pragma unroll
        for (int j = 0; j < NEXP; j++) { l[j] = acc[j] + bg[j]; mx = fmaxf(mx, l[j]); }
        float s = 0.f;
#pragma unroll
        for (int j = 0; j < NEXP; j++) { l[j] = expf(l[j] - mx); s += l[j]; }
        float inv = 1.f / s;
#pragma unroll
        for (int j = 0; j < NEXP; j++) l[j] *= inv;
        int i0 = 0;
#pragma unroll
        for (int j = 1; j < NEXP; j++) if (l[j] > l[i0]) i0 = j;
        int i1 = (i0 == 0) ? 1 : 0;
#pragma unroll
        for (int j = 0; j < NEXP; j++) if (j != i0 && j != i1 && l[j] > l[i1]) i1 = j;
#pragma unroll
        for (int j = 0; j < NEXP; j++) if (j != i0 && j < i1 && l[j] >= l[i1]) i1 = j;
        int p0 = atomicAdd(&g_cnt[i0], 1);
        int p1 = atomicAdd(&g_cnt[i1], 1);
        g_tok[i0 * TOKS + p0] = t;
        g_tok[i1 * TOKS + p1] = t;
        g_ase[t * 2 + 0] = i0; g_asp[t * 2 + 0] = p0; g_asw[t * 2 + 0] = l[i0];
        g_ase[t * 2 + 1] = i1; g_asp[t * 2 + 1] = p1; g_asw[t * 2 + 1] = l[i1];
    }
}

// ---------------- kernel 2: exclusive scan ----------------
__global__ void scan_kernel() {
    if (threadIdx.x == 0) {
        int s = 0;
        for (int e = 0; e < NEXP; e++) { g_base[e] = s; s += g_cnt[e]; }
    }
}

// ---------------- kernel 3: transpose + fp16 convert, 64x32 tiles ----------------
// src [E][R][C] fp32 -> dst [E][C][R] fp16.  Reads 128B rows, writes 128B rows.
__global__ void __launch_bounds__(256) transpose_kernel(const float* __restrict__ src,
                                                        int which, int R, int C) {
    __shared__ float tile[64][33];
    __half* dst = which ? g_W2t : g_W1t;
    const int e = blockIdx.z, r0 = blockIdx.y * 64, c0 = blockIdx.x * 32;
    const float* s = src + (size_t)e * R * C;
    __half* d = dst + (size_t)e * C * R;
    const int tid = threadIdx.x;
    const int hc = tid & 31, dr0 = tid >> 5;
#pragma unroll
    for (int i = 0; i < 8; i++)
        tile[dr0 + i * 8][hc] = s[(size_t)(r0 + dr0 + i * 8) * C + c0 + hc];
    __syncthreads();
    const int h = tid >> 3, ch = tid & 7;     // output row (c), 8-half chunk (r)
    __half hv[8];
#pragma unroll
    for (int j = 0; j < 8; j++) hv[j] = __float2half_rn(tile[ch * 8 + j][h]);
    *(uint4*)(d + (size_t)(c0 + h) * R + r0 + ch * 8) = *(uint4*)hv;
}

// ---------------- kernel 4: fp16 mma.sync GEMM (both phases) ----------------
// grid: (rtile, e, ntile)
template <int PHASE>
__global__ void __launch_bounds__(256, 2) gemm_kernel(const float* __restrict__ bias) {
    constexpr int Kdim = (PHASE == 1) ? DIM : HID;
    constexpr int Ntot = (PHASE == 1) ? HID : DIM;
    constexpr int NK = Kdim / KC;

    const int rtile = blockIdx.x, e = blockIdx.y, ntile = blockIdx.z;
    const int cnt = g_cnt[e];
    const int r_lo = rtile * MT;
    if (r_lo >= cnt) return;
    const int base = g_base[e];
    const int tid = threadIdx.x, wid = tid >> 5, lane = tid & 31;

    extern __shared__ char smem[];
    const uint32_t smA = smem_u32(smem);            // stage s at smA + s*STAGE_BYTES
    const uint32_t smB = smA + A_ST;

    const __half* Abase = (PHASE == 1) ? g_xr : g_h;
    const __half* Brow0 = ((PHASE == 1) ? g_W1t : g_W2t)
                          + ((size_t)e * Ntot + (size_t)ntile * NT) * Kdim;   // [n][k]
    const int* tokp = g_tok + e * TOKS;

    auto load_stage = [&](int kt) {
        const uint32_t sb = (uint32_t)(kt % NSTAGE) * STAGE_BYTES;
        const int k0 = kt * KC;
#pragma unroll
        for (int i = 0; i < 2; i++) {            // A: 128 rows x 4 segs of 16B (8 halves)
            int c = tid + i * 256;
            int r = c >> 2, seg = c & 3;
            int rg = r_lo + r;
            bool ok = rg < cnt;
            const __half* src;
            if (PHASE == 1)
                src = Abase + (size_t)(ok ? tokp[rg] : 0) * Kdim + k0 + seg * 8;
            else
                src = Abase + (size_t)(base + (ok ? rg : 0)) * Kdim + k0 + seg * 8;
            cp16(smA + sb + (uint32_t)(r * TSTRIDE + seg * 16), src, ok);
        }
#pragma unroll
        for (int i = 0; i < 2; i++) {            // B: 128 n-rows x 4 segs
            int c = tid + i * 256;
            int n = c >> 2, seg = c & 3;
            cp16(smB + sb + (uint32_t)(n * TSTRIDE + seg * 16),
                 Brow0 + (size_t)n * Kdim + k0 + seg * 8, true);
        }
        CP_COMMIT();
    };

    // warp tile: 64(m) x 32(n); 2 warps in m, 4 warps in n
    const int wm = (wid & 1) * 64;
    const int wn = (wid >> 1) * 32;
    // A ldmatrix lane offset (16B chunk = 8 halves = k8)
    const int amat = lane >> 3;                              // 0..3
    const uint32_t aOff = (uint32_t)((wm + (amat & 1) * 8 + (lane & 7)) * TSTRIDE
                                     + (amat >> 1) * 16);
    // B ldmatrix x4 lane offset: 4 matrices = {n0-7,k0-7},{n0-7,k8-15},{n8-15,k0-7},{n8-15,k8-15}
    const uint32_t bOff = (uint32_t)((wn + ((lane >> 4) & 1) * 8 + (lane & 7)) * TSTRIDE
                                     + ((lane >> 3) & 1) * 16);

    float acc[4][4][4];
#pragma unroll
    for (int mt = 0; mt < 4; mt++)
#pragma unroll
        for (int nt = 0; nt < 4; nt++)
#pragma unroll
            for (int q = 0; q < 4; q++) acc[mt][nt][q] = 0.f;

#pragma unroll
    for (int s = 0; s < NSTAGE - 1; s++) load_stage(s);

    for (int kt = 0; kt < NK; kt++) {
        if (kt < NK - 1) asm volatile("cp.async.wait_group %0;" :: "n"(NSTAGE - 2) : "memory");
        else             asm volatile("cp.async.wait_group 0;" ::: "memory");
        __syncthreads();
        if (kt + NSTAGE - 1 < NK) load_stage(kt + NSTAGE - 1);

        const uint32_t sb = (uint32_t)(kt % NSTAGE) * STAGE_BYTES;
        const uint32_t aBase = smA + sb + aOff;
        const uint32_t bBase = smB + sb + bOff;
#pragma unroll
        for (int ks = 0; ks < 2; ks++) {         // two k16 steps per 32-k stage
            uint32_t af[4][4], bf[2][4];
#pragma unroll
            for (int mt = 0; mt < 4; mt++)
                ldsm_x4(af[mt], aBase + (uint32_t)(mt * 16 * TSTRIDE + ks * 32));
#pragma unroll
            for (int p = 0; p < 2; p++)          // each x4 covers two n8 tiles
                ldsm_x4(bf[p], bBase + (uint32_t)(p * 16 * TSTRIDE + ks * 32));
#pragma unroll
            for (int mt = 0; mt < 4; mt++)
#pragma unroll
                for (int nt = 0; nt < 4; nt++)
                    mma_f16(acc[mt][nt], af[mt], bf[nt >> 1] + (nt & 1) * 2);
        }
    }

    // epilogue — fp16 output for both phases
    const int row_in = lane >> 2;
    const int col_in = (lane & 3) * 2;
    __half* Cbase = (PHASE == 1) ? g_h : g_y;
    const float* brow = bias + (size_t)e * Ntot;
#pragma unroll
    for (int mt = 0; mt < 4; mt++) {
#pragma unroll
        for (int half = 0; half < 2; half++) {
            int r = r_lo + wm + mt * 16 + row_in + half * 8;
            if (r < cnt) {
#pragma unroll
                for (int nt = 0; nt < 4; nt++) {
                    int col = ntile * NT + wn + nt * 8 + col_in;
                    float v0 = acc[mt][nt][half * 2 + 0] + brow[col];
                    float v1 = acc[mt][nt][half * 2 + 1] + brow[col + 1];
                    if (PHASE == 1) { v0 = fmaxf(v0, 0.f); v1 = fmaxf(v1, 0.f); }
                    __half2 hv;
                    hv.x = __float2half_rn(v0);
                    hv.y = __float2half_rn(v1);
                    *(__half2*)(Cbase + (size_t)(base + r) * Ntot + col) = hv;
                }
            }
        }
    }
}

// ---------------- kernel 5: weighted combine (fp16 y -> fp32 out) ----------------
__global__ void __launch_bounds__(256) combine_kernel(float* __restrict__ out) {
    const int t = blockIdx.x;
    const int s0 = g_base[g_ase[t * 2 + 0]] + g_asp[t * 2 + 0];
    const int s1 = g_base[g_ase[t * 2 + 1]] + g_asp[t * 2 + 1];
    const float w0 = g_asw[t * 2 + 0], w1 = g_asw[t * 2 + 1];
    const uint2* y0 = (const uint2*)(g_y + (size_t)s0 * DIM);
    const uint2* y1 = (const uint2*)(g_y + (size_t)s1 * DIM);
    float4* o = (float4*)(out + (size_t)t * DIM);
    const int i = threadIdx.x;   // 256 threads * 4 halves = 1024 = DIM
    uint2 a = y0[i], b = y1[i];
    float2 a0 = __half22float2(*(__half2*)&a.x);
    float2 a1 = __half22float2(*(__half2*)&a.y);
    float2 b0 = __half22float2(*(__half2*)&b.x);
    float2 b1 = __half22float2(*(__half2*)&b.y);
    float4 r;
    r.x = w0 * a0.x + w1 * b0.x;
    r.y = w0 * a0.y + w1 * b0.y;
    r.z = w0 * a1.x + w1 * b1.x;
    r.w = w0 * a1.y + w1 * b1.y;
    o[i] = r;
}

// ---------------- launch ----------------
extern "C" void kernel_launch(void* const* d_in, const int* in_sizes, int n_in,
                              void* d_out, int out_size) {
    const float* x  = (const float*)d_in[0];
    const float* Wg = (const float*)d_in[1];
    const float* bg = (const float*)d_in[2];
    const float* W1 = (const float*)d_in[3];
    const float* b1 = (const float*)d_in[4];
    const float* W2 = (const float*)d_in[5];
    const float* b2 = (const float*)d_in[6];
    float* out = (float*)d_out;

    static cudaStream_t s1 = nullptr, s2 = nullptr;
    static cudaEvent_t evF = nullptr, ev1 = nullptr, ev2 = nullptr;
    if (s1 == nullptr) {
        cudaStreamCreateWithFlags(&s1, cudaStreamNonBlocking);
        cudaStreamCreateWithFlags(&s2, cudaStreamNonBlocking);
        cudaEventCreateWithFlags(&evF, cudaEventDisableTiming);
        cudaEventCreateWithFlags(&ev1, cudaEventDisableTiming);
        cudaEventCreateWithFlags(&ev2, cudaEventDisableTiming);
        cudaFuncSetAttribute(gemm_kernel<1>, cudaFuncAttributeMaxDynamicSharedMemorySize, SMEM_DYN);
        cudaFuncSetAttribute(gemm_kernel<2>, cudaFuncAttributeMaxDynamicSharedMemorySize, SMEM_DYN);
    }

    // fork side streams off the capture-origin (default) stream
    cudaEventRecord(evF, 0);
    cudaStreamWaitEvent(s1, evF, 0);
    cudaStreamWaitEvent(s2, evF, 0);
    // W1 [E][D][H] -> g_W1t [E][H][D]  (R=D, C=H)   — overlaps gating
    transpose_kernel<<<dim3(HID / 32, DIM / 64, NEXP), 256, 0, s1>>>(W1, 0, DIM, HID);
    cudaEventRecord(ev1, s1);
    // W2 [E][H][D] -> g_W2t [E][D][H]  (R=H, C=D)   — overlaps gating + GEMM1
    transpose_kernel<<<dim3(DIM / 32, HID / 64, NEXP), 256, 0, s2>>>(W2, 1, HID, DIM);
    cudaEventRecord(ev2, s2);

    zero_kernel<<<1, 32>>>();
    gating_kernel<<<TOKS / 8, 256>>>(x, Wg, bg);
    scan_kernel<<<1, 32>>>();

    cudaStreamWaitEvent(0, ev1, 0);
    gemm_kernel<1><<<dim3(TOKS / MT, NEXP, HID / NT), 256, SMEM_DYN>>>(b1);
    cudaStreamWaitEvent(0, ev2, 0);
    gemm_kernel<2><<<dim3(TOKS / MT, NEXP, DIM / NT), 256, SMEM_DYN>>>(b2);
    combine_kernel<<<TOKS, 256>>>(out);
}